// round 9
// baseline (speedup 1.0000x reference)
#include <cuda_runtime.h>
#include <cstdint>

// Problem constants
#define S_LEN  1024
#define HID    1024
#define NH     16
#define DK     64
#define BATCH  4
#define M_TOT  (BATCH * S_LEN)     // 4096
#define QK_SCALE 0.125f            // 64^-0.5
#define NEGV   (-9e15f)

// Scratch (static device globals — allocation-free per harness rules)
__device__ __align__(256) float g_q[BATCH * NH * S_LEN * DK];   // tf32, pre-scaled
__device__ __align__(256) float g_k[BATCH * NH * S_LEN * DK];   // tf32
__device__ __align__(256) float g_v[BATCH * NH * S_LEN * DK];   // tf32
__device__ __align__(256) float g_att[BATCH * S_LEN * HID];     // tf32 (attn out)
__device__ __align__(256) float g_x [M_TOT * HID];              // tf32 batch
__device__ __align__(256) float g_wq[HID * HID];                // tf32 weights
__device__ __align__(256) float g_wk[HID * HID];
__device__ __align__(256) float g_wv[HID * HID];
__device__ __align__(256) float g_wo[HID * HID];

__device__ __forceinline__ uint32_t f2tf32(float f) {
    uint32_t r;
    asm("cvt.rna.tf32.f32 %0, %1;" : "=r"(r) : "f"(f));
    return r;
}
__device__ __forceinline__ float tf32f(float f) {
    return __uint_as_float(f2tf32(f));
}
__device__ __forceinline__ uint32_t smem_u32(const void* p) {
    uint32_t a;
    asm("{ .reg .u64 t; cvta.to.shared.u64 t, %1; cvt.u32.u64 %0, t; }"
        : "=r"(a) : "l"(p));
    return a;
}
__device__ __forceinline__ void cpasync16(uint32_t dst, const void* src) {
    asm volatile("cp.async.ca.shared.global [%0], [%1], 16;"
                 :: "r"(dst), "l"(src) : "memory");
}
__device__ __forceinline__ void cpasync_commit() {
    asm volatile("cp.async.commit_group;" ::: "memory");
}
__device__ __forceinline__ void cpasync_wait0() {
    asm volatile("cp.async.wait_group 0;" ::: "memory");
}
__device__ __forceinline__ void cpasync_wait1() {
    asm volatile("cp.async.wait_group 1;" ::: "memory");
}

__device__ __forceinline__ void mma_tf32(float c[4], const uint32_t a[4],
                                         const uint32_t b[2]) {
    asm volatile(
        "mma.sync.aligned.m16n8k8.row.col.f32.tf32.tf32.f32 "
        "{%0,%1,%2,%3}, {%4,%5,%6,%7}, {%8,%9}, {%0,%1,%2,%3};"
        : "+f"(c[0]), "+f"(c[1]), "+f"(c[2]), "+f"(c[3])
        : "r"(a[0]), "r"(a[1]), "r"(a[2]), "r"(a[3]),
          "r"(b[0]), "r"(b[1]));
}

// Fast exp on the FMA pipe. Rel err ~4e-5. Valid for |x| < ~85.
__device__ __forceinline__ float fexp(float x) {
    float z = x * 1.44269504f;
    z = fmaxf(z, -125.0f);
    const float C = 12582912.0f;            // 1.5 * 2^23
    float nf = z + C;
    int n = __float_as_int(nf) - 0x4B400000;
    float f = z - (nf - C);
    float p = 0.00961813f;
    p = fmaf(p, f, 0.0555041f);
    p = fmaf(p, f, 0.240227f);
    p = fmaf(p, f, 0.693147f);
    p = fmaf(p, f, 1.0f);
    return __int_as_float(__float_as_int(p) + (n << 23));
}

// ---------------------------------------------------------------------------
// Fused pre-round pass: batch + 4 weights -> tf32 scratch (single launch).
// ---------------------------------------------------------------------------
#define N4X (M_TOT * HID / 4)   // 1048576
#define N4W (HID * HID / 4)     // 262144

__global__ __launch_bounds__(256) void round_all(
    const float4* __restrict__ x,
    const float4* __restrict__ wq, const float4* __restrict__ wk,
    const float4* __restrict__ wv, const float4* __restrict__ wo,
    float4* __restrict__ ox,
    float4* __restrict__ owq, float4* __restrict__ owk,
    float4* __restrict__ owv, float4* __restrict__ owo)
{
    const int i = blockIdx.x * 256 + threadIdx.x;
    const float4* src;
    float4* dst;
    int off;
    if (i < N4X) {
        src = x; dst = ox; off = i;
    } else {
        const int j = i - N4X;
        const int sel = j >> 18;              // N4W = 2^18
        off = j & (N4W - 1);
        src = sel == 0 ? wq : (sel == 1 ? wk : (sel == 2 ? wv : wo));
        dst = sel == 0 ? owq : (sel == 1 ? owk : (sel == 2 ? owv : owo));
    }
    float4 v = src[off];
    v.x = tf32f(v.x); v.y = tf32f(v.y);
    v.z = tf32f(v.z); v.w = tf32f(v.w);
    dst[off] = v;
}

// ---------------------------------------------------------------------------
// GEMM core: TF32 mma.sync, 128x128 tile, BK=32, 8 warps,
// 3-stage cp.async pipeline; fragment loads software-pipelined across the
// 4 k-steps (double-buffered by parity) to hide LDS latency behind MMAs.
// ---------------------------------------------------------------------------
#define PAD    36
#define TILEF  (128 * PAD)
#define STAGEF (2 * TILEF)
#define GEMM_SMEM_BYTES (3 * STAGEF * 4) // 110592

#define LOAD_STAGE(s, kk)                                                     \
    do {                                                                      \
        const uint32_t base = sbase + (uint32_t)(s) * (STAGEF * 4);           \
        _Pragma("unroll")                                                     \
        for (int t = 0; t < 4; ++t) {                                         \
            const int idx = tid + t * 256;                                    \
            const int row = idx >> 3, c4 = idx & 7;                           \
            cpasync16(base + row * (PAD * 4) + c4 * 16,                       \
                      Ap + (size_t)(bm + row) * 1024 + (kk) + c4 * 4);        \
            cpasync16(base + TILEF * 4 + row * (PAD * 4) + c4 * 16,           \
                      Wp + (size_t)(bn + row) * 1024 + (kk) + c4 * 4);        \
        }                                                                     \
        cpasync_commit();                                                     \
    } while (0)

#define LOAD_FRAGS(pb, kb)                                                    \
    do {                                                                      \
        _Pragma("unroll")                                                     \
        for (int mi = 0; mi < 2; ++mi) {                                      \
            const int r0 = (wm * 32 + mi * 16 + g) * PAD + (kb) + tg;         \
            af[pb][mi][0] = __float_as_uint(As[r0]);                          \
            af[pb][mi][1] = __float_as_uint(As[r0 + 8 * PAD]);                \
            af[pb][mi][2] = __float_as_uint(As[r0 + 4]);                      \
            af[pb][mi][3] = __float_as_uint(As[r0 + 8 * PAD + 4]);            \
        }                                                                     \
        _Pragma("unroll")                                                     \
        for (int ni = 0; ni < 8; ++ni) {                                      \
            const int r0 = (wn * 64 + ni * 8 + g) * PAD + (kb) + tg;          \
            bf[pb][ni][0] = __float_as_uint(Ws[r0]);                          \
            bf[pb][ni][1] = __float_as_uint(Ws[r0 + 4]);                      \
        }                                                                     \
    } while (0)

#define GEMM_MAINLOOP()                                                       \
    LOAD_STAGE(0, 0);                                                         \
    LOAD_STAGE(1, 32);                                                        \
    for (int i = 0; i < 32; ++i) {                                            \
        if (i >= 30) cpasync_wait0(); else cpasync_wait1();                   \
        __syncthreads();                                                      \
        if (i + 2 < 32) {                                                     \
            const int s2 = (i + 2) % 3;                                       \
            LOAD_STAGE(s2, (i + 2) * 32);                                     \
        }                                                                     \
        const float* As = sm + (i % 3) * STAGEF;                              \
        const float* Ws = As + TILEF;                                         \
        uint32_t af[2][2][4];                                                 \
        uint32_t bf[2][8][2];                                                 \
        LOAD_FRAGS(0, 0);                                                     \
        _Pragma("unroll")                                                     \
        for (int ks = 0; ks < 4; ++ks) {                                      \
            const int pb = ks & 1;                                            \
            if (ks < 3) { LOAD_FRAGS(pb ^ 1, (ks + 1) * 8); }                 \
            _Pragma("unroll")                                                 \
            for (int mi = 0; mi < 2; ++mi)                                    \
                _Pragma("unroll")                                             \
                for (int ni = 0; ni < 8; ++ni)                                \
                    mma_tf32(c[mi][ni], af[pb][mi], bf[pb][ni]);              \
        }                                                                     \
    }

// Fused QKV projection: grid (24, 32); bx>>3 selects {Q,K,V}.
__global__ __launch_bounds__(256, 2) void gemm_qkv(
    const float* __restrict__ A,
    const float* __restrict__ Wqp, const float* __restrict__ Wkp,
    const float* __restrict__ Wvp,
    const float* __restrict__ bq, const float* __restrict__ bk,
    const float* __restrict__ bv,
    float* __restrict__ oq, float* __restrict__ ok, float* __restrict__ ov)
{
    extern __shared__ float sm[];
    const uint32_t sbase = smem_u32(sm);

    const int tid = threadIdx.x;
    const int wid = tid >> 5, lid = tid & 31;
    const int which = blockIdx.x >> 3;
    const int bn = (blockIdx.x & 7) * 128;
    const int bm = blockIdx.y * 128;
    const int wm = wid >> 1, wn = wid & 1;
    const int g = lid >> 2, tg = lid & 3;

    const float* Wp   = which == 0 ? Wqp : (which == 1 ? Wkp : Wvp);
    const float* bias = which == 0 ? bq  : (which == 1 ? bk  : bv);
    float* out        = which == 0 ? oq  : (which == 1 ? ok  : ov);
    const float scale = which == 0 ? QK_SCALE : 1.0f;
    const float* Ap = A;

    float c[2][8][4];
#pragma unroll
    for (int mi = 0; mi < 2; ++mi)
#pragma unroll
        for (int ni = 0; ni < 8; ++ni)
#pragma unroll
            for (int k = 0; k < 4; ++k) c[mi][ni][k] = 0.0f;

    GEMM_MAINLOOP();

#pragma unroll
    for (int mi = 0; mi < 2; ++mi) {
        const int rowa = bm + wm * 32 + mi * 16 + g;
        const int rowb = rowa + 8;
#pragma unroll
        for (int ni = 0; ni < 8; ++ni) {
            const int col = bn + wn * 64 + ni * 8 + tg * 2;
            const float b0 = bias[col], b1 = bias[col + 1];
            float2 v0 = make_float2(tf32f((c[mi][ni][0] + b0) * scale),
                                    tf32f((c[mi][ni][1] + b1) * scale));
            float2 v1 = make_float2(tf32f((c[mi][ni][2] + b0) * scale),
                                    tf32f((c[mi][ni][3] + b1) * scale));
            const int h = col >> 6, d = col & 63;
            const int ba = rowa >> 10, sa = rowa & 1023;
            const int bb = rowb >> 10, sb2 = rowb & 1023;
            *(float2*)(out + (((size_t)(ba * NH + h) * S_LEN + sa) * DK + d)) = v0;
            *(float2*)(out + (((size_t)(bb * NH + h) * S_LEN + sb2) * DK + d)) = v1;
        }
    }
}

// Output projection: row-major fp32 out.
__global__ __launch_bounds__(256, 2) void gemm_o(
    const float* __restrict__ A, const float* __restrict__ W,
    const float* __restrict__ bias, float* __restrict__ out)
{
    extern __shared__ float sm[];
    const uint32_t sbase = smem_u32(sm);

    const int tid = threadIdx.x;
    const int wid = tid >> 5, lid = tid & 31;
    const int bn = blockIdx.x * 128;
    const int bm = blockIdx.y * 128;
    const int wm = wid >> 1, wn = wid & 1;
    const int g = lid >> 2, tg = lid & 3;
    const float* Ap = A;
    const float* Wp = W;

    float c[2][8][4];
#pragma unroll
    for (int mi = 0; mi < 2; ++mi)
#pragma unroll
        for (int ni = 0; ni < 8; ++ni)
#pragma unroll
            for (int k = 0; k < 4; ++k) c[mi][ni][k] = 0.0f;

    GEMM_MAINLOOP();

#pragma unroll
    for (int mi = 0; mi < 2; ++mi) {
        const int rowa = bm + wm * 32 + mi * 16 + g;
        const int rowb = rowa + 8;
#pragma unroll
        for (int ni = 0; ni < 8; ++ni) {
            const int col = bn + wn * 64 + ni * 8 + tg * 2;
            const float b0 = bias[col], b1 = bias[col + 1];
            *(float2*)(out + (size_t)rowa * HID + col) =
                make_float2(c[mi][ni][0] + b0, c[mi][ni][1] + b1);
            *(float2*)(out + (size_t)rowb * HID + col) =
                make_float2(c[mi][ni][2] + b0, c[mi][ni][3] + b1);
        }
    }
}

// ---------------------------------------------------------------------------
// Tensor-core flash attention (tf32 mma.sync). K-tiles of 32.
// Fixed-zero-max softmax. cp.async double-buffered K, V, bias.
// Register-shuffled P. CTA: 128 q, 8 warps x 16 q-rows. (unchanged R8)
// ---------------------------------------------------------------------------
#define APAD   68
#define BPAD   36
#define ROWB   (APAD * 4)
#define QS_F   0
#define K0_F   (128 * APAD)
#define K1_F   (K0_F + 32 * APAD)
#define V0_F   (K1_F + 32 * APAD)
#define V1_F   (V0_F + 32 * APAD)
#define B0_F   (V1_F + 32 * APAD)
#define B1_F   (B0_F + 128 * BPAD)
#define ATTN_SMEM_BYTES ((B1_F + 128 * BPAD) * 4) // 106496

#define KT_N   32
#define NTILES (S_LEN / KT_N)                     // 32

__global__ __launch_bounds__(256, 2) void attn_mma(
    const float* __restrict__ Qg, const float* __restrict__ Kg,
    const float* __restrict__ Vg, const float* __restrict__ Bias,
    float* __restrict__ O)
{
    extern __shared__ float sm[];
    const uint32_t sb = smem_u32(sm);
    const uint32_t QSb = sb + QS_F * 4;
    const uint32_t Kb[2] = { sb + K0_F * 4, sb + K1_F * 4 };
    const uint32_t Vb[2] = { sb + V0_F * 4, sb + V1_F * 4 };
    const uint32_t Bb[2] = { sb + B0_F * 4, sb + B1_F * 4 };
    float* Qs = sm + QS_F;
    float* Kf[2] = { sm + K0_F, sm + K1_F };
    float* Vf[2] = { sm + V0_F, sm + V1_F };
    float* Bf[2] = { sm + B0_F, sm + B1_F };

    const int q0 = blockIdx.x * 128;
    const int h  = blockIdx.y;
    const int b  = blockIdx.z;
    const int bh = b * NH + h;

    const float* qp = Qg + (size_t)bh * S_LEN * DK + (size_t)q0 * DK;
    const float* kp = Kg + (size_t)bh * S_LEN * DK;
    const float* vp = Vg + (size_t)bh * S_LEN * DK;
    const float* bp = Bias + (size_t)bh * S_LEN * S_LEN + (size_t)q0 * S_LEN;

    const int tid = threadIdx.x;
    const int wid = tid >> 5, lid = tid & 31;
    const int g = lid >> 2, tg = lid & 3;
    const int qb = wid * 16;
    const int qrow0 = q0 + qb + g;

#define LOAD_TILE(st, kt)                                                     \
    do {                                                                      \
        const float* kpn = kp + (size_t)(kt) * KT_N * 64;                     \
        const float* vpn = vp + (size_t)(kt) * KT_N * 64;                     \
        const float* bpn = bp + (kt) * KT_N;                                  \
        _Pragma("unroll")                                                     \
        for (int i2 = 0; i2 < 2; ++i2) {                                      \
            const int cidx = tid + i2 * 256;                                  \
            const int row = cidx >> 4, off = cidx & 15;                       \
            cpasync16(Kb[st] + row * ROWB + off * 16, kpn + row * 64 + off * 4); \
            cpasync16(Vb[st] + row * ROWB + off * 16, vpn + row * 64 + off * 4); \
        }                                                                     \
        _Pragma("unroll")                                                     \
        for (int i2 = 0; i2 < 4; ++i2) {                                      \
            const int cidx = tid + i2 * 256;                                  \
            const int row = cidx >> 3, off = cidx & 7;                        \
            cpasync16(Bb[st] + (row * BPAD + off * 4) * 4,                    \
                      bpn + (size_t)row * S_LEN + off * 4);                   \
        }                                                                     \
        cpasync_commit();                                                     \
    } while (0)

    // Prologue: Q tile + tile 0
#pragma unroll
    for (int i = 0; i < 8; ++i) {
        const int cidx = tid + i * 256;
        const int row = cidx >> 4, off = cidx & 15;
        cpasync16(QSb + row * ROWB + off * 16, qp + row * 64 + off * 4);
    }
    LOAD_TILE(0, 0);

    float l0 = 0.0f, l1 = 0.0f;
    float acc[8][4];
#pragma unroll
    for (int ni = 0; ni < 8; ++ni)
#pragma unroll
        for (int j = 0; j < 4; ++j) acc[ni][j] = 0.0f;

    for (int kt = 0; kt < NTILES; ++kt) {
        cpasync_wait0();
        __syncthreads();
        const int cur = kt & 1;

        if (kt + 1 < NTILES) LOAD_TILE(cur ^ 1, kt + 1);

        // S = Q @ K^T  (warp: 16 q x 32 k)
        float s[4][4];
#pragma unroll
        for (int ni = 0; ni < 4; ++ni)
#pragma unroll
            for (int j = 0; j < 4; ++j) s[ni][j] = 0.0f;
        const float* Kcur = Kf[cur];
#pragma unroll
        for (int kc = 0; kc < 64; kc += 8) {
            uint32_t a[4];
            const float* qa = Qs + (qb + g) * APAD + kc + tg;
            a[0] = __float_as_uint(qa[0]);
            a[1] = __float_as_uint(qa[8 * APAD]);
            a[2] = __float_as_uint(qa[4]);
            a[3] = __float_as_uint(qa[8 * APAD + 4]);
#pragma unroll
            for (int ni = 0; ni < 4; ++ni) {
                uint32_t bb[2];
                const float* kb2 = Kcur + (ni * 8 + g) * APAD + kc + tg;
                bb[0] = __float_as_uint(kb2[0]);
                bb[1] = __float_as_uint(kb2[4]);
                mma_tf32(s[ni], a, bb);
            }
        }

        // mask + bias + exp (no max subtraction — scores bounded), P -> tf32
        const float* Bcur = Bf[cur];
#pragma unroll
        for (int ni = 0; ni < 4; ++ni) {
            const int bco = ni * 8 + tg * 2;
            float2 b0 = *(const float2*)(Bcur + (qb + g) * BPAD + bco);
            float2 b1 = *(const float2*)(Bcur + (qb + g + 8) * BPAD + bco);
            const float p00 = fexp((s[ni][0] == 0.0f ? NEGV : s[ni][0]) + b0.x);
            const float p01 = fexp((s[ni][1] == 0.0f ? NEGV : s[ni][1]) + b0.y);
            const float p10 = fexp((s[ni][2] == 0.0f ? NEGV : s[ni][2]) + b1.x);
            const float p11 = fexp((s[ni][3] == 0.0f ? NEGV : s[ni][3]) + b1.y);
            l0 += p00 + p01;
            l1 += p10 + p11;
            s[ni][0] = tf32f(p00); s[ni][1] = tf32f(p01);
            s[ni][2] = tf32f(p10); s[ni][3] = tf32f(p11);
        }

        // acc += P @ V : A-fragment from S-fragment via lane shuffles.
        const float* Vcur = Vf[cur];
        const int src0 = (lid & 28) | (tg >> 1);
        const int src1 = src0 + 2;
        const bool odd = (tg & 1) != 0;
#pragma unroll
        for (int kcb = 0; kcb < 4; ++kcb) {
            const float v0 = __shfl_sync(0xffffffffu, s[kcb][0], src0);
            const float v1 = __shfl_sync(0xffffffffu, s[kcb][1], src0);
            const float v2 = __shfl_sync(0xffffffffu, s[kcb][2], src0);
            const float v3 = __shfl_sync(0xffffffffu, s[kcb][3], src0);
            const float w0 = __shfl_sync(0xffffffffu, s[kcb][0], src1);
            const float w1 = __shfl_sync(0xffffffffu, s[kcb][1], src1);
            const float w2 = __shfl_sync(0xffffffffu, s[kcb][2], src1);
            const float w3 = __shfl_sync(0xffffffffu, s[kcb][3], src1);
            uint32_t a[4];
            a[0] = __float_as_uint(odd ? v1 : v0);
            a[1] = __float_as_uint(odd ? v3 : v2);
            a[2] = __float_as_uint(odd ? w1 : w0);
            a[3] = __float_as_uint(odd ? w3 : w2);
            const int kc = kcb * 8;
#pragma unroll
            for (int ni = 0; ni < 8; ++ni) {
                uint32_t bb[2];
                const float* vb = Vcur + (kc + tg) * APAD + ni * 8 + g;
                bb[0] = __float_as_uint(vb[0]);
                bb[1] = __float_as_uint(vb[4 * APAD]);
                mma_tf32(acc[ni], a, bb);
            }
        }
    }

    // Row sums: single quad reduction at the end (no rescaling was done).
    l0 += __shfl_xor_sync(0xffffffffu, l0, 1);
    l0 += __shfl_xor_sync(0xffffffffu, l0, 2);
    l1 += __shfl_xor_sync(0xffffffffu, l1, 1);
    l1 += __shfl_xor_sync(0xffffffffu, l1, 2);

    // Epilogue: normalize, tf32-round (O-proj A operand), store [b][s][hid]
    const float inv0 = 1.0f / l0;
    const float inv1 = 1.0f / l1;
#pragma unroll
    for (int ni = 0; ni < 8; ++ni) {
        const int col = h * DK + ni * 8 + tg * 2;
        float* o0 = O + (size_t)(b * S_LEN + qrow0) * HID + col;
        float* o1 = O + (size_t)(b * S_LEN + qrow0 + 8) * HID + col;
        *(float2*)o0 = make_float2(tf32f(acc[ni][0] * inv0), tf32f(acc[ni][1] * inv0));
        *(float2*)o1 = make_float2(tf32f(acc[ni][2] * inv1), tf32f(acc[ni][3] * inv1));
    }
}

// ---------------------------------------------------------------------------
extern "C" void kernel_launch(void* const* d_in, const int* in_sizes, int n_in,
                              void* d_out, int out_size)
{
    const float* batch = (const float*)d_in[0];
    const float* bias  = (const float*)d_in[1];
    const float* Wq = (const float*)d_in[2];
    const float* bq = (const float*)d_in[3];
    const float* Wk = (const float*)d_in[4];
    const float* bk = (const float*)d_in[5];
    const float* Wv = (const float*)d_in[6];
    const float* bv = (const float*)d_in[7];
    const float* Wo = (const float*)d_in[8];
    const float* bo = (const float*)d_in[9];
    float* out = (float*)d_out;

    float *qptr, *kptr, *vptr, *aptr, *xptr, *wqp, *wkp, *wvp, *wop;
    cudaGetSymbolAddress((void**)&qptr, g_q);
    cudaGetSymbolAddress((void**)&kptr, g_k);
    cudaGetSymbolAddress((void**)&vptr, g_v);
    cudaGetSymbolAddress((void**)&aptr, g_att);
    cudaGetSymbolAddress((void**)&xptr, g_x);
    cudaGetSymbolAddress((void**)&wqp, g_wq);
    cudaGetSymbolAddress((void**)&wkp, g_wk);
    cudaGetSymbolAddress((void**)&wvp, g_wv);
    cudaGetSymbolAddress((void**)&wop, g_wo);

    static int attr_set = 0;
    if (!attr_set) {
        cudaFuncSetAttribute(gemm_qkv,
                             cudaFuncAttributeMaxDynamicSharedMemorySize,
                             GEMM_SMEM_BYTES);
        cudaFuncSetAttribute(gemm_o,
                             cudaFuncAttributeMaxDynamicSharedMemorySize,
                             GEMM_SMEM_BYTES);
        cudaFuncSetAttribute(attn_mma,
                             cudaFuncAttributeMaxDynamicSharedMemorySize,
                             ATTN_SMEM_BYTES);
        attr_set = 1;
    }

    const int total4 = N4X + 4 * N4W;      // 2097152
    round_all<<<total4 / 256, 256>>>(
        (const float4*)batch, (const float4*)Wq, (const float4*)Wk,
        (const float4*)Wv, (const float4*)Wo,
        (float4*)xptr, (float4*)wqp, (float4*)wkp, (float4*)wvp, (float4*)wop);

    dim3 qkvgrid(24, 32);
    gemm_qkv<<<qkvgrid, 256, GEMM_SMEM_BYTES>>>(xptr, wqp, wkp, wvp,
                                                bq, bk, bv, qptr, kptr, vptr);

    dim3 agrid(S_LEN / 128, NH, BATCH);
    attn_mma<<<agrid, 256, ATTN_SMEM_BYTES>>>(qptr, kptr, vptr, bias, aptr);

    dim3 ogrid(HID / 128, M_TOT / 128);
    gemm_o<<<ogrid, 256, GEMM_SMEM_BYTES>>>(aptr, wop, bo, out);
}

// round 10
// speedup vs baseline: 1.2798x; 1.2798x over previous
#include <cuda_runtime.h>
#include <cuda_fp16.h>
#include <cstdint>

// Problem constants
#define S_LEN  1024
#define HID    1024
#define NH     16
#define DK     64
#define BATCH  4
#define M_TOT  (BATCH * S_LEN)     // 4096
#define QK_SCALE 0.125f            // 64^-0.5
#define NEGV   (-9e15f)

// Scratch (static device globals — allocation-free per harness rules)
__device__ __align__(256) float  g_q[BATCH * NH * S_LEN * DK];   // tf32, pre-scaled
__device__ __align__(256) float  g_k[BATCH * NH * S_LEN * DK];   // tf32
__device__ __align__(256) float  g_v[BATCH * NH * S_LEN * DK];   // tf32
__device__ __align__(256) __half g_att16[M_TOT * HID];           // attn out (fp16)
__device__ __align__(256) __half g_x16 [M_TOT * HID];            // fp16 batch
__device__ __align__(256) __half g_wq16[HID * HID];              // fp16 weights
__device__ __align__(256) __half g_wk16[HID * HID];
__device__ __align__(256) __half g_wv16[HID * HID];
__device__ __align__(256) __half g_wo16[HID * HID];

__device__ __forceinline__ uint32_t f2tf32(float f) {
    uint32_t r;
    asm("cvt.rna.tf32.f32 %0, %1;" : "=r"(r) : "f"(f));
    return r;
}
__device__ __forceinline__ float tf32f(float f) {
    return __uint_as_float(f2tf32(f));
}
__device__ __forceinline__ uint32_t smem_u32(const void* p) {
    uint32_t a;
    asm("{ .reg .u64 t; cvta.to.shared.u64 t, %1; cvt.u32.u64 %0, t; }"
        : "=r"(a) : "l"(p));
    return a;
}
__device__ __forceinline__ void cpasync16(uint32_t dst, const void* src) {
    asm volatile("cp.async.ca.shared.global [%0], [%1], 16;"
                 :: "r"(dst), "l"(src) : "memory");
}
__device__ __forceinline__ void cpasync_commit() {
    asm volatile("cp.async.commit_group;" ::: "memory");
}
__device__ __forceinline__ void cpasync_wait0() {
    asm volatile("cp.async.wait_group 0;" ::: "memory");
}
__device__ __forceinline__ void cpasync_wait1() {
    asm volatile("cp.async.wait_group 1;" ::: "memory");
}

// fp16 MMA, fp32 accumulate: D(16x8) += A(16x16) * B(16x8)
__device__ __forceinline__ void mma_f16(float c[4], const uint32_t a[4],
                                        const uint32_t b[2]) {
    asm volatile(
        "mma.sync.aligned.m16n8k16.row.col.f32.f16.f16.f32 "
        "{%0,%1,%2,%3}, {%4,%5,%6,%7}, {%8,%9}, {%0,%1,%2,%3};"
        : "+f"(c[0]), "+f"(c[1]), "+f"(c[2]), "+f"(c[3])
        : "r"(a[0]), "r"(a[1]), "r"(a[2]), "r"(a[3]),
          "r"(b[0]), "r"(b[1]));
}

// tf32 MMA (attention path, unchanged)
__device__ __forceinline__ void mma_tf32(float c[4], const uint32_t a[4],
                                         const uint32_t b[2]) {
    asm volatile(
        "mma.sync.aligned.m16n8k8.row.col.f32.tf32.tf32.f32 "
        "{%0,%1,%2,%3}, {%4,%5,%6,%7}, {%8,%9}, {%0,%1,%2,%3};"
        : "+f"(c[0]), "+f"(c[1]), "+f"(c[2]), "+f"(c[3])
        : "r"(a[0]), "r"(a[1]), "r"(a[2]), "r"(a[3]),
          "r"(b[0]), "r"(b[1]));
}

// Fast exp on the FMA pipe. Rel err ~4e-5.
__device__ __forceinline__ float fexp(float x) {
    float z = x * 1.44269504f;
    z = fmaxf(z, -125.0f);
    const float C = 12582912.0f;            // 1.5 * 2^23
    float nf = z + C;
    int n = __float_as_int(nf) - 0x4B400000;
    float f = z - (nf - C);
    float p = 0.00961813f;
    p = fmaf(p, f, 0.0555041f);
    p = fmaf(p, f, 0.240227f);
    p = fmaf(p, f, 0.693147f);
    p = fmaf(p, f, 1.0f);
    return __int_as_float(__float_as_int(p) + (n << 23));
}

// ---------------------------------------------------------------------------
// Pre-round pass: batch + 4 weights -> fp16 scratch (single launch).
// Each thread converts 8 floats (two float4 reads, one uint4 write).
// ---------------------------------------------------------------------------
#define G8X (M_TOT * HID / 8)   // 524288
#define G8W (HID * HID / 8)     // 131072 = 2^17

__global__ __launch_bounds__(256) void round_all16(
    const float4* __restrict__ x,
    const float4* __restrict__ wq, const float4* __restrict__ wk,
    const float4* __restrict__ wv, const float4* __restrict__ wo,
    __half* __restrict__ ox,
    __half* __restrict__ owq, __half* __restrict__ owk,
    __half* __restrict__ owv, __half* __restrict__ owo)
{
    const int i = blockIdx.x * 256 + threadIdx.x;
    const float4* src;
    __half* dst;
    int off;
    if (i < G8X) {
        src = x; dst = ox; off = i;
    } else {
        const int j = i - G8X;
        const int sel = j >> 17;
        off = j & (G8W - 1);
        src = sel == 0 ? wq : (sel == 1 ? wk : (sel == 2 ? wv : wo));
        dst = sel == 0 ? owq : (sel == 1 ? owk : (sel == 2 ? owv : owo));
    }
    float4 v0 = src[off * 2];
    float4 v1 = src[off * 2 + 1];
    __half2 h[4];
    h[0] = __float22half2_rn(make_float2(v0.x, v0.y));
    h[1] = __float22half2_rn(make_float2(v0.z, v0.w));
    h[2] = __float22half2_rn(make_float2(v1.x, v1.y));
    h[3] = __float22half2_rn(make_float2(v1.z, v1.w));
    *(uint4*)(dst + (size_t)off * 8) = *(const uint4*)h;
}

// ---------------------------------------------------------------------------
// GEMM core: FP16 mma.sync (m16n8k16, fp32 accum), 128x128 tile, BK=32,
// 8 warps, 3-stage cp.async pipeline. Smem rows: 32 fp16, pitch 40 fp16
// (80B: 16B-aligned for cp.async, conflict-free fragment loads).
// ---------------------------------------------------------------------------
#define PITCHB  80
#define TILEB   (128 * PITCHB)          // 10240 B per operand tile
#define STAGEB  (2 * TILEB)             // 20480
#define GEMM_SMEM_BYTES (3 * STAGEB)    // 61440

#define LOAD_STAGE(s, kk)                                                     \
    do {                                                                      \
        const uint32_t base = sbase + (uint32_t)(s) * STAGEB;                 \
        _Pragma("unroll")                                                     \
        for (int t = 0; t < 2; ++t) {                                         \
            const int idx = tid + t * 256;                                    \
            const int row = idx >> 2, c4 = idx & 3;                           \
            cpasync16(base + row * PITCHB + c4 * 16,                          \
                      Ap + (size_t)(bm + row) * 1024 + (kk) + c4 * 8);        \
            cpasync16(base + TILEB + row * PITCHB + c4 * 16,                  \
                      Wp + (size_t)(bn + row) * 1024 + (kk) + c4 * 8);        \
        }                                                                     \
        cpasync_commit();                                                     \
    } while (0)

#define GEMM_MAINLOOP16()                                                     \
    LOAD_STAGE(0, 0);                                                         \
    LOAD_STAGE(1, 32);                                                        \
    for (int i = 0; i < 32; ++i) {                                            \
        if (i >= 30) cpasync_wait0(); else cpasync_wait1();                   \
        __syncthreads();                                                      \
        if (i + 2 < 32) {                                                     \
            const int s2 = (i + 2) % 3;                                       \
            LOAD_STAGE(s2, (i + 2) * 32);                                     \
        }                                                                     \
        const char* Sb = (const char*)sm + (i % 3) * STAGEB;                  \
        _Pragma("unroll")                                                     \
        for (int ks = 0; ks < 2; ++ks) {                                      \
            const int kbB = ks * 32;                                          \
            uint32_t af[2][4];                                                \
            _Pragma("unroll")                                                 \
            for (int mi = 0; mi < 2; ++mi) {                                  \
                const char* p = Sb + (wm * 32 + mi * 16 + g) * PITCHB         \
                                + kbB + tg * 4;                               \
                af[mi][0] = *(const uint32_t*)(p);                            \
                af[mi][1] = *(const uint32_t*)(p + 8 * PITCHB);               \
                af[mi][2] = *(const uint32_t*)(p + 16);                       \
                af[mi][3] = *(const uint32_t*)(p + 8 * PITCHB + 16);          \
            }                                                                 \
            uint32_t bf[8][2];                                                \
            _Pragma("unroll")                                                 \
            for (int ni = 0; ni < 8; ++ni) {                                  \
                const char* p = Sb + TILEB + (wn * 64 + ni * 8 + g) * PITCHB  \
                                + kbB + tg * 4;                               \
                bf[ni][0] = *(const uint32_t*)(p);                            \
                bf[ni][1] = *(const uint32_t*)(p + 16);                       \
            }                                                                 \
            _Pragma("unroll")                                                 \
            for (int mi = 0; mi < 2; ++mi)                                    \
                _Pragma("unroll")                                             \
                for (int ni = 0; ni < 8; ++ni)                                \
                    mma_f16(c[mi][ni], af[mi], bf[ni]);                       \
        }                                                                     \
    }

// Fused QKV projection: grid (24, 32); bx>>3 selects {Q,K,V}.
// Outputs fp32 tf32-rounded (Q pre-scaled) for the tf32 attention.
__global__ __launch_bounds__(256, 2) void gemm_qkv(
    const __half* __restrict__ A,
    const __half* __restrict__ Wqp, const __half* __restrict__ Wkp,
    const __half* __restrict__ Wvp,
    const float* __restrict__ bq, const float* __restrict__ bk,
    const float* __restrict__ bv,
    float* __restrict__ oq, float* __restrict__ ok, float* __restrict__ ov)
{
    extern __shared__ float sm[];
    const uint32_t sbase = smem_u32(sm);

    const int tid = threadIdx.x;
    const int wid = tid >> 5, lid = tid & 31;
    const int which = blockIdx.x >> 3;
    const int bn = (blockIdx.x & 7) * 128;
    const int bm = blockIdx.y * 128;
    const int wm = wid >> 1, wn = wid & 1;
    const int g = lid >> 2, tg = lid & 3;

    const __half* Wp  = which == 0 ? Wqp : (which == 1 ? Wkp : Wvp);
    const float* bias = which == 0 ? bq  : (which == 1 ? bk  : bv);
    float* out        = which == 0 ? oq  : (which == 1 ? ok  : ov);
    const float scale = which == 0 ? QK_SCALE : 1.0f;
    const __half* Ap = A;

    float c[2][8][4];
#pragma unroll
    for (int mi = 0; mi < 2; ++mi)
#pragma unroll
        for (int ni = 0; ni < 8; ++ni)
#pragma unroll
            for (int k = 0; k < 4; ++k) c[mi][ni][k] = 0.0f;

    GEMM_MAINLOOP16();

#pragma unroll
    for (int mi = 0; mi < 2; ++mi) {
        const int rowa = bm + wm * 32 + mi * 16 + g;
        const int rowb = rowa + 8;
#pragma unroll
        for (int ni = 0; ni < 8; ++ni) {
            const int col = bn + wn * 64 + ni * 8 + tg * 2;
            const float b0 = bias[col], b1 = bias[col + 1];
            float2 v0 = make_float2(tf32f((c[mi][ni][0] + b0) * scale),
                                    tf32f((c[mi][ni][1] + b1) * scale));
            float2 v1 = make_float2(tf32f((c[mi][ni][2] + b0) * scale),
                                    tf32f((c[mi][ni][3] + b1) * scale));
            const int h = col >> 6, d = col & 63;
            const int ba = rowa >> 10, sa = rowa & 1023;
            const int bb = rowb >> 10, sb2 = rowb & 1023;
            *(float2*)(out + (((size_t)(ba * NH + h) * S_LEN + sa) * DK + d)) = v0;
            *(float2*)(out + (((size_t)(bb * NH + h) * S_LEN + sb2) * DK + d)) = v1;
        }
    }
}

// Output projection: fp16 inputs, row-major fp32 out.
__global__ __launch_bounds__(256, 2) void gemm_o(
    const __half* __restrict__ A, const __half* __restrict__ W,
    const float* __restrict__ bias, float* __restrict__ out)
{
    extern __shared__ float sm[];
    const uint32_t sbase = smem_u32(sm);

    const int tid = threadIdx.x;
    const int wid = tid >> 5, lid = tid & 31;
    const int bn = blockIdx.x * 128;
    const int bm = blockIdx.y * 128;
    const int wm = wid >> 1, wn = wid & 1;
    const int g = lid >> 2, tg = lid & 3;
    const __half* Ap = A;
    const __half* Wp = W;

    float c[2][8][4];
#pragma unroll
    for (int mi = 0; mi < 2; ++mi)
#pragma unroll
        for (int ni = 0; ni < 8; ++ni)
#pragma unroll
            for (int k = 0; k < 4; ++k) c[mi][ni][k] = 0.0f;

    GEMM_MAINLOOP16();

#pragma unroll
    for (int mi = 0; mi < 2; ++mi) {
        const int rowa = bm + wm * 32 + mi * 16 + g;
        const int rowb = rowa + 8;
#pragma unroll
        for (int ni = 0; ni < 8; ++ni) {
            const int col = bn + wn * 64 + ni * 8 + tg * 2;
            const float b0 = bias[col], b1 = bias[col + 1];
            *(float2*)(out + (size_t)rowa * HID + col) =
                make_float2(c[mi][ni][0] + b0, c[mi][ni][1] + b1);
            *(float2*)(out + (size_t)rowb * HID + col) =
                make_float2(c[mi][ni][2] + b0, c[mi][ni][3] + b1);
        }
    }
}

// ---------------------------------------------------------------------------
// Tensor-core flash attention (tf32 mma.sync). K-tiles of 32.
// Fixed-zero-max softmax. cp.async double-buffered K, V, bias.
// Register-shuffled P. CTA: 128 q, 8 warps x 16 q-rows. (R8 structure;
// epilogue writes fp16 for the fp16 O-projection.)
// ---------------------------------------------------------------------------
#define APAD   68
#define BPAD   36
#define ROWB   (APAD * 4)
#define QS_F   0
#define K0_F   (128 * APAD)
#define K1_F   (K0_F + 32 * APAD)
#define V0_F   (K1_F + 32 * APAD)
#define V1_F   (V0_F + 32 * APAD)
#define B0_F   (V1_F + 32 * APAD)
#define B1_F   (B0_F + 128 * BPAD)
#define ATTN_SMEM_BYTES ((B1_F + 128 * BPAD) * 4) // 106496

#define KT_N   32
#define NTILES (S_LEN / KT_N)                     // 32

__global__ __launch_bounds__(256, 2) void attn_mma(
    const float* __restrict__ Qg, const float* __restrict__ Kg,
    const float* __restrict__ Vg, const float* __restrict__ Bias,
    __half* __restrict__ O)
{
    extern __shared__ float sm[];
    const uint32_t sb = smem_u32(sm);
    const uint32_t QSb = sb + QS_F * 4;
    const uint32_t Kb[2] = { sb + K0_F * 4, sb + K1_F * 4 };
    const uint32_t Vb[2] = { sb + V0_F * 4, sb + V1_F * 4 };
    const uint32_t Bb[2] = { sb + B0_F * 4, sb + B1_F * 4 };
    float* Qs = sm + QS_F;
    float* Kf[2] = { sm + K0_F, sm + K1_F };
    float* Vf[2] = { sm + V0_F, sm + V1_F };
    float* Bf[2] = { sm + B0_F, sm + B1_F };

    const int q0 = blockIdx.x * 128;
    const int h  = blockIdx.y;
    const int b  = blockIdx.z;
    const int bh = b * NH + h;

    const float* qp = Qg + (size_t)bh * S_LEN * DK + (size_t)q0 * DK;
    const float* kp = Kg + (size_t)bh * S_LEN * DK;
    const float* vp = Vg + (size_t)bh * S_LEN * DK;
    const float* bp = Bias + (size_t)bh * S_LEN * S_LEN + (size_t)q0 * S_LEN;

    const int tid = threadIdx.x;
    const int wid = tid >> 5, lid = tid & 31;
    const int g = lid >> 2, tg = lid & 3;
    const int qb = wid * 16;
    const int qrow0 = q0 + qb + g;

#define LOAD_TILE(st, kt)                                                     \
    do {                                                                      \
        const float* kpn = kp + (size_t)(kt) * KT_N * 64;                     \
        const float* vpn = vp + (size_t)(kt) * KT_N * 64;                     \
        const float* bpn = bp + (kt) * KT_N;                                  \
        _Pragma("unroll")                                                     \
        for (int i2 = 0; i2 < 2; ++i2) {                                      \
            const int cidx = tid + i2 * 256;                                  \
            const int row = cidx >> 4, off = cidx & 15;                       \
            cpasync16(Kb[st] + row * ROWB + off * 16, kpn + row * 64 + off * 4); \
            cpasync16(Vb[st] + row * ROWB + off * 16, vpn + row * 64 + off * 4); \
        }                                                                     \
        _Pragma("unroll")                                                     \
        for (int i2 = 0; i2 < 4; ++i2) {                                      \
            const int cidx = tid + i2 * 256;                                  \
            const int row = cidx >> 3, off = cidx & 7;                        \
            cpasync16(Bb[st] + (row * BPAD + off * 4) * 4,                    \
                      bpn + (size_t)row * S_LEN + off * 4);                   \
        }                                                                     \
        cpasync_commit();                                                     \
    } while (0)

    // Prologue: Q tile + tile 0
#pragma unroll
    for (int i = 0; i < 8; ++i) {
        const int cidx = tid + i * 256;
        const int row = cidx >> 4, off = cidx & 15;
        cpasync16(QSb + row * ROWB + off * 16, qp + row * 64 + off * 4);
    }
    LOAD_TILE(0, 0);

    float l0 = 0.0f, l1 = 0.0f;
    float acc[8][4];
#pragma unroll
    for (int ni = 0; ni < 8; ++ni)
#pragma unroll
        for (int j = 0; j < 4; ++j) acc[ni][j] = 0.0f;

    for (int kt = 0; kt < NTILES; ++kt) {
        cpasync_wait0();
        __syncthreads();
        const int cur = kt & 1;

        if (kt + 1 < NTILES) LOAD_TILE(cur ^ 1, kt + 1);

        // S = Q @ K^T  (warp: 16 q x 32 k)
        float s[4][4];
#pragma unroll
        for (int ni = 0; ni < 4; ++ni)
#pragma unroll
            for (int j = 0; j < 4; ++j) s[ni][j] = 0.0f;
        const float* Kcur = Kf[cur];
#pragma unroll
        for (int kc = 0; kc < 64; kc += 8) {
            uint32_t a[4];
            const float* qa = Qs + (qb + g) * APAD + kc + tg;
            a[0] = __float_as_uint(qa[0]);
            a[1] = __float_as_uint(qa[8 * APAD]);
            a[2] = __float_as_uint(qa[4]);
            a[3] = __float_as_uint(qa[8 * APAD + 4]);
#pragma unroll
            for (int ni = 0; ni < 4; ++ni) {
                uint32_t bb[2];
                const float* kb2 = Kcur + (ni * 8 + g) * APAD + kc + tg;
                bb[0] = __float_as_uint(kb2[0]);
                bb[1] = __float_as_uint(kb2[4]);
                mma_tf32(s[ni], a, bb);
            }
        }

        // mask + bias + exp (no max subtraction — scores bounded), P -> tf32
        const float* Bcur = Bf[cur];
#pragma unroll
        for (int ni = 0; ni < 4; ++ni) {
            const int bco = ni * 8 + tg * 2;
            float2 b0 = *(const float2*)(Bcur + (qb + g) * BPAD + bco);
            float2 b1 = *(const float2*)(Bcur + (qb + g + 8) * BPAD + bco);
            const float p00 = fexp((s[ni][0] == 0.0f ? NEGV : s[ni][0]) + b0.x);
            const float p01 = fexp((s[ni][1] == 0.0f ? NEGV : s[ni][1]) + b0.y);
            const float p10 = fexp((s[ni][2] == 0.0f ? NEGV : s[ni][2]) + b1.x);
            const float p11 = fexp((s[ni][3] == 0.0f ? NEGV : s[ni][3]) + b1.y);
            l0 += p00 + p01;
            l1 += p10 + p11;
            s[ni][0] = tf32f(p00); s[ni][1] = tf32f(p01);
            s[ni][2] = tf32f(p10); s[ni][3] = tf32f(p11);
        }

        // acc += P @ V : A-fragment from S-fragment via lane shuffles.
        const float* Vcur = Vf[cur];
        const int src0 = (lid & 28) | (tg >> 1);
        const int src1 = src0 + 2;
        const bool odd = (tg & 1) != 0;
#pragma unroll
        for (int kcb = 0; kcb < 4; ++kcb) {
            const float v0 = __shfl_sync(0xffffffffu, s[kcb][0], src0);
            const float v1 = __shfl_sync(0xffffffffu, s[kcb][1], src0);
            const float v2 = __shfl_sync(0xffffffffu, s[kcb][2], src0);
            const float v3 = __shfl_sync(0xffffffffu, s[kcb][3], src0);
            const float w0 = __shfl_sync(0xffffffffu, s[kcb][0], src1);
            const float w1 = __shfl_sync(0xffffffffu, s[kcb][1], src1);
            const float w2 = __shfl_sync(0xffffffffu, s[kcb][2], src1);
            const float w3 = __shfl_sync(0xffffffffu, s[kcb][3], src1);
            uint32_t a[4];
            a[0] = __float_as_uint(odd ? v1 : v0);
            a[1] = __float_as_uint(odd ? v3 : v2);
            a[2] = __float_as_uint(odd ? w1 : w0);
            a[3] = __float_as_uint(odd ? w3 : w2);
            const int kc = kcb * 8;
#pragma unroll
            for (int ni = 0; ni < 8; ++ni) {
                uint32_t bb[2];
                const float* vb = Vcur + (kc + tg) * APAD + ni * 8 + g;
                bb[0] = __float_as_uint(vb[0]);
                bb[1] = __float_as_uint(vb[4 * APAD]);
                mma_tf32(acc[ni], a, bb);
            }
        }
    }

    // Row sums: single quad reduction at the end (no rescaling was done).
    l0 += __shfl_xor_sync(0xffffffffu, l0, 1);
    l0 += __shfl_xor_sync(0xffffffffu, l0, 2);
    l1 += __shfl_xor_sync(0xffffffffu, l1, 1);
    l1 += __shfl_xor_sync(0xffffffffu, l1, 2);

    // Epilogue: normalize, fp16 (O-proj A operand), store [b][s][hid]
    const float inv0 = 1.0f / l0;
    const float inv1 = 1.0f / l1;
#pragma unroll
    for (int ni = 0; ni < 8; ++ni) {
        const int col = h * DK + ni * 8 + tg * 2;
        __half* o0 = O + (size_t)(b * S_LEN + qrow0) * HID + col;
        __half* o1 = O + (size_t)(b * S_LEN + qrow0 + 8) * HID + col;
        *(__half2*)o0 = __float22half2_rn(
            make_float2(acc[ni][0] * inv0, acc[ni][1] * inv0));
        *(__half2*)o1 = __float22half2_rn(
            make_float2(acc[ni][2] * inv1, acc[ni][3] * inv1));
    }
}

// ---------------------------------------------------------------------------
extern "C" void kernel_launch(void* const* d_in, const int* in_sizes, int n_in,
                              void* d_out, int out_size)
{
    const float* batch = (const float*)d_in[0];
    const float* bias  = (const float*)d_in[1];
    const float* Wq = (const float*)d_in[2];
    const float* bq = (const float*)d_in[3];
    const float* Wk = (const float*)d_in[4];
    const float* bk = (const float*)d_in[5];
    const float* Wv = (const float*)d_in[6];
    const float* bv = (const float*)d_in[7];
    const float* Wo = (const float*)d_in[8];
    const float* bo = (const float*)d_in[9];
    float* out = (float*)d_out;

    float *qptr, *kptr, *vptr;
    __half *aptr, *xptr, *wqp, *wkp, *wvp, *wop;
    cudaGetSymbolAddress((void**)&qptr, g_q);
    cudaGetSymbolAddress((void**)&kptr, g_k);
    cudaGetSymbolAddress((void**)&vptr, g_v);
    cudaGetSymbolAddress((void**)&aptr, g_att16);
    cudaGetSymbolAddress((void**)&xptr, g_x16);
    cudaGetSymbolAddress((void**)&wqp, g_wq16);
    cudaGetSymbolAddress((void**)&wkp, g_wk16);
    cudaGetSymbolAddress((void**)&wvp, g_wv16);
    cudaGetSymbolAddress((void**)&wop, g_wo16);

    static int attr_set = 0;
    if (!attr_set) {
        cudaFuncSetAttribute(gemm_qkv,
                             cudaFuncAttributeMaxDynamicSharedMemorySize,
                             GEMM_SMEM_BYTES);
        cudaFuncSetAttribute(gemm_o,
                             cudaFuncAttributeMaxDynamicSharedMemorySize,
                             GEMM_SMEM_BYTES);
        cudaFuncSetAttribute(attn_mma,
                             cudaFuncAttributeMaxDynamicSharedMemorySize,
                             ATTN_SMEM_BYTES);
        attr_set = 1;
    }

    const int totalG = G8X + 4 * G8W;      // 1048576 threads
    round_all16<<<totalG / 256, 256>>>(
        (const float4*)batch, (const float4*)Wq, (const float4*)Wk,
        (const float4*)Wv, (const float4*)Wo,
        xptr, wqp, wkp, wvp, wop);

    dim3 qkvgrid(24, 32);
    gemm_qkv<<<qkvgrid, 256, GEMM_SMEM_BYTES>>>(xptr, wqp, wkp, wvp,
                                                bq, bk, bv, qptr, kptr, vptr);

    dim3 agrid(S_LEN / 128, NH, BATCH);
    attn_mma<<<agrid, 256, ATTN_SMEM_BYTES>>>(qptr, kptr, vptr, bias, aptr);

    dim3 ogrid(HID / 128, M_TOT / 128);
    gemm_o<<<ogrid, 256, GEMM_SMEM_BYTES>>>(aptr, wop, bo, out);
}

// round 11
// speedup vs baseline: 1.6911x; 1.3214x over previous
#include <cuda_runtime.h>
#include <cuda_fp16.h>
#include <cstdint>

// Problem constants
#define S_LEN  1024
#define HID    1024
#define NH     16
#define DK     64
#define BATCH  4
#define M_TOT  (BATCH * S_LEN)     // 4096
#define QK_SCALE 0.125f            // 64^-0.5
#define NEGV   (-9e15f)

// Scratch (static device globals — allocation-free per harness rules)
__device__ __align__(256) __half g_q16 [BATCH * NH * S_LEN * DK];  // [b][h][s][d], pre-scaled
__device__ __align__(256) __half g_k16 [BATCH * NH * S_LEN * DK];  // [b][h][s][d]
__device__ __align__(256) __half g_vt16[BATCH * NH * DK * S_LEN];  // [b][h][d][s]  (V^T)
__device__ __align__(256) __half g_att16[M_TOT * HID];             // attn out
__device__ __align__(256) __half g_x16 [M_TOT * HID];              // fp16 batch
__device__ __align__(256) __half g_wq16[HID * HID];
__device__ __align__(256) __half g_wk16[HID * HID];
__device__ __align__(256) __half g_wv16[HID * HID];
__device__ __align__(256) __half g_wo16[HID * HID];

__device__ __forceinline__ uint32_t smem_u32(const void* p) {
    uint32_t a;
    asm("{ .reg .u64 t; cvta.to.shared.u64 t, %1; cvt.u32.u64 %0, t; }"
        : "=r"(a) : "l"(p));
    return a;
}
__device__ __forceinline__ void cpasync16(uint32_t dst, const void* src) {
    asm volatile("cp.async.ca.shared.global [%0], [%1], 16;"
                 :: "r"(dst), "l"(src) : "memory");
}
__device__ __forceinline__ void cpasync_commit() {
    asm volatile("cp.async.commit_group;" ::: "memory");
}
__device__ __forceinline__ void cpasync_wait0() {
    asm volatile("cp.async.wait_group 0;" ::: "memory");
}
__device__ __forceinline__ void cpasync_wait1() {
    asm volatile("cp.async.wait_group 1;" ::: "memory");
}

// fp16 MMA, fp32 accumulate: D(16x8) += A(16x16) * B(16x8)
__device__ __forceinline__ void mma_f16(float c[4], const uint32_t a[4],
                                        const uint32_t b[2]) {
    asm volatile(
        "mma.sync.aligned.m16n8k16.row.col.f32.f16.f16.f32 "
        "{%0,%1,%2,%3}, {%4,%5,%6,%7}, {%8,%9}, {%0,%1,%2,%3};"
        : "+f"(c[0]), "+f"(c[1]), "+f"(c[2]), "+f"(c[3])
        : "r"(a[0]), "r"(a[1]), "r"(a[2]), "r"(a[3]),
          "r"(b[0]), "r"(b[1]));
}

// Fast exp on the FMA pipe. Rel err ~4e-5.
__device__ __forceinline__ float fexp(float x) {
    float z = x * 1.44269504f;
    z = fmaxf(z, -125.0f);
    const float C = 12582912.0f;            // 1.5 * 2^23
    float nf = z + C;
    int n = __float_as_int(nf) - 0x4B400000;
    float f = z - (nf - C);
    float p = 0.00961813f;
    p = fmaf(p, f, 0.0555041f);
    p = fmaf(p, f, 0.240227f);
    p = fmaf(p, f, 0.693147f);
    p = fmaf(p, f, 1.0f);
    return __int_as_float(__float_as_int(p) + (n << 23));
}

// ---------------------------------------------------------------------------
// Pre-round pass: batch + 4 weights -> fp16 scratch (single launch).
// ---------------------------------------------------------------------------
#define G8X (M_TOT * HID / 8)   // 524288
#define G8W (HID * HID / 8)     // 131072 = 2^17

__global__ __launch_bounds__(256) void round_all16(
    const float4* __restrict__ x,
    const float4* __restrict__ wq, const float4* __restrict__ wk,
    const float4* __restrict__ wv, const float4* __restrict__ wo,
    __half* __restrict__ ox,
    __half* __restrict__ owq, __half* __restrict__ owk,
    __half* __restrict__ owv, __half* __restrict__ owo)
{
    const int i = blockIdx.x * 256 + threadIdx.x;
    const float4* src;
    __half* dst;
    int off;
    if (i < G8X) {
        src = x; dst = ox; off = i;
    } else {
        const int j = i - G8X;
        const int sel = j >> 17;
        off = j & (G8W - 1);
        src = sel == 0 ? wq : (sel == 1 ? wk : (sel == 2 ? wv : wo));
        dst = sel == 0 ? owq : (sel == 1 ? owk : (sel == 2 ? owv : owo));
    }
    float4 v0 = src[off * 2];
    float4 v1 = src[off * 2 + 1];
    __half2 h[4];
    h[0] = __float22half2_rn(make_float2(v0.x, v0.y));
    h[1] = __float22half2_rn(make_float2(v0.z, v0.w));
    h[2] = __float22half2_rn(make_float2(v1.x, v1.y));
    h[3] = __float22half2_rn(make_float2(v1.z, v1.w));
    *(uint4*)(dst + (size_t)off * 8) = *(const uint4*)h;
}

// ---------------------------------------------------------------------------
// GEMM core: FP16 mma.sync (m16n8k16, fp32 accum), 128x128 tile, BK=32,
// 8 warps, 3-stage cp.async pipeline. Rows: 32 fp16, pitch 80 B.
// ---------------------------------------------------------------------------
#define PITCHB  80
#define TILEB   (128 * PITCHB)          // 10240 B per operand tile
#define STAGEB  (2 * TILEB)             // 20480
#define GEMM_SMEM_BYTES (3 * STAGEB)    // 61440

#define LOAD_STAGE(s, kk)                                                     \
    do {                                                                      \
        const uint32_t base = sbase + (uint32_t)(s) * STAGEB;                 \
        _Pragma("unroll")                                                     \
        for (int t = 0; t < 2; ++t) {                                         \
            const int idx = tid + t * 256;                                    \
            const int row = idx >> 2, c4 = idx & 3;                           \
            cpasync16(base + row * PITCHB + c4 * 16,                          \
                      Ap + (size_t)(bm + row) * 1024 + (kk) + c4 * 8);        \
            cpasync16(base + TILEB + row * PITCHB + c4 * 16,                  \
                      Wp + (size_t)(bn + row) * 1024 + (kk) + c4 * 8);        \
        }                                                                     \
        cpasync_commit();                                                     \
    } while (0)

#define GEMM_MAINLOOP16()                                                     \
    LOAD_STAGE(0, 0);                                                         \
    LOAD_STAGE(1, 32);                                                        \
    for (int i = 0; i < 32; ++i) {                                            \
        if (i >= 30) cpasync_wait0(); else cpasync_wait1();                   \
        __syncthreads();                                                      \
        if (i + 2 < 32) {                                                     \
            const int s2 = (i + 2) % 3;                                       \
            LOAD_STAGE(s2, (i + 2) * 32);                                     \
        }                                                                     \
        const char* Sb = (const char*)sm + (i % 3) * STAGEB;                  \
        _Pragma("unroll")                                                     \
        for (int ks = 0; ks < 2; ++ks) {                                      \
            const int kbB = ks * 32;                                          \
            uint32_t af[2][4];                                                \
            _Pragma("unroll")                                                 \
            for (int mi = 0; mi < 2; ++mi) {                                  \
                const char* p = Sb + (wm * 32 + mi * 16 + g) * PITCHB         \
                                + kbB + tg * 4;                               \
                af[mi][0] = *(const uint32_t*)(p);                            \
                af[mi][1] = *(const uint32_t*)(p + 8 * PITCHB);               \
                af[mi][2] = *(const uint32_t*)(p + 16);                       \
                af[mi][3] = *(const uint32_t*)(p + 8 * PITCHB + 16);          \
            }                                                                 \
            uint32_t bf[8][2];                                                \
            _Pragma("unroll")                                                 \
            for (int ni = 0; ni < 8; ++ni) {                                  \
                const char* p = Sb + TILEB + (wn * 64 + ni * 8 + g) * PITCHB  \
                                + kbB + tg * 4;                               \
                bf[ni][0] = *(const uint32_t*)(p);                            \
                bf[ni][1] = *(const uint32_t*)(p + 16);                       \
            }                                                                 \
            _Pragma("unroll")                                                 \
            for (int mi = 0; mi < 2; ++mi)                                    \
                _Pragma("unroll")                                             \
                for (int ni = 0; ni < 8; ++ni)                                \
                    mma_f16(c[mi][ni], af[mi], bf[ni]);                       \
        }                                                                     \
    }

// Fused QKV projection: grid (24, 32); bx>>3 selects {Q,K,V}.
// Q/K: fp16 [b][h][s][d] (Q pre-scaled). V: fp16 TRANSPOSED [b][h][d][s]
// via smem-staged transpose for coalesced writes.
__global__ __launch_bounds__(256, 2) void gemm_qkv(
    const __half* __restrict__ A,
    const __half* __restrict__ Wqp, const __half* __restrict__ Wkp,
    const __half* __restrict__ Wvp,
    const float* __restrict__ bq, const float* __restrict__ bk,
    const float* __restrict__ bv,
    __half* __restrict__ oq, __half* __restrict__ ok, __half* __restrict__ ovt)
{
    extern __shared__ float sm[];
    const uint32_t sbase = smem_u32(sm);

    const int tid = threadIdx.x;
    const int wid = tid >> 5, lid = tid & 31;
    const int which = blockIdx.x >> 3;
    const int bn = (blockIdx.x & 7) * 128;
    const int bm = blockIdx.y * 128;
    const int wm = wid >> 1, wn = wid & 1;
    const int g = lid >> 2, tg = lid & 3;

    const __half* Wp  = which == 0 ? Wqp : (which == 1 ? Wkp : Wvp);
    const float* bias = which == 0 ? bq  : (which == 1 ? bk  : bv);
    const __half* Ap = A;

    float c[2][8][4];
#pragma unroll
    for (int mi = 0; mi < 2; ++mi)
#pragma unroll
        for (int ni = 0; ni < 8; ++ni)
#pragma unroll
            for (int k = 0; k < 4; ++k) c[mi][ni][k] = 0.0f;

    GEMM_MAINLOOP16();

    if (which < 2) {
        __half* out = which == 0 ? oq : ok;
        const float scale = which == 0 ? QK_SCALE : 1.0f;
#pragma unroll
        for (int mi = 0; mi < 2; ++mi) {
            const int rowa = bm + wm * 32 + mi * 16 + g;
            const int rowb = rowa + 8;
#pragma unroll
            for (int ni = 0; ni < 8; ++ni) {
                const int col = bn + wn * 64 + ni * 8 + tg * 2;
                const float b0 = bias[col], b1 = bias[col + 1];
                __half2 h0 = __float22half2_rn(
                    make_float2((c[mi][ni][0] + b0) * scale,
                                (c[mi][ni][1] + b1) * scale));
                __half2 h1 = __float22half2_rn(
                    make_float2((c[mi][ni][2] + b0) * scale,
                                (c[mi][ni][3] + b1) * scale));
                const int h = col >> 6, d = col & 63;
                const int ba = rowa >> 10, sa = rowa & 1023;
                const int bb = rowb >> 10, sb2 = rowb & 1023;
                *(__half2*)(out + (((size_t)(ba * NH + h) * S_LEN + sa) * DK + d)) = h0;
                *(__half2*)(out + (((size_t)(bb * NH + h) * S_LEN + sb2) * DK + d)) = h1;
            }
        }
    } else {
        // V: stage transposed [n][m] fp16 tile (pitch 136 halfs = 34816 B)
        __syncthreads();
        __half* st = (__half*)sm;
#pragma unroll
        for (int mi = 0; mi < 2; ++mi) {
            const int ma = wm * 32 + mi * 16 + g;
            const int mb = ma + 8;
#pragma unroll
            for (int ni = 0; ni < 8; ++ni) {
                const int nl = wn * 64 + ni * 8 + tg * 2;
                const float b0 = bias[bn + nl], b1 = bias[bn + nl + 1];
                st[(nl + 0) * 136 + ma] = __float2half_rn(c[mi][ni][0] + b0);
                st[(nl + 1) * 136 + ma] = __float2half_rn(c[mi][ni][1] + b1);
                st[(nl + 0) * 136 + mb] = __float2half_rn(c[mi][ni][2] + b0);
                st[(nl + 1) * 136 + mb] = __float2half_rn(c[mi][ni][3] + b1);
            }
        }
        __syncthreads();
        const int r = tid >> 1, sel = tid & 1;
        const int col = bn + r;
        const int hh = col >> 6, d = col & 63;
        const int bb2 = bm >> 10;
        const int s0 = (bm & 1023) + sel * 64;
        __half* dst = ovt + (((size_t)(bb2 * NH + hh) * DK + d) * S_LEN + s0);
        const __half* srcp = st + r * 136 + sel * 64;
#pragma unroll
        for (int k2 = 0; k2 < 8; ++k2)
            *(uint4*)(dst + k2 * 8) = *(const uint4*)(srcp + k2 * 8);
    }
}

// Output projection: fp16 inputs, row-major fp32 out. (unchanged R10)
__global__ __launch_bounds__(256, 2) void gemm_o(
    const __half* __restrict__ A, const __half* __restrict__ W,
    const float* __restrict__ bias, float* __restrict__ out)
{
    extern __shared__ float sm[];
    const uint32_t sbase = smem_u32(sm);

    const int tid = threadIdx.x;
    const int wid = tid >> 5, lid = tid & 31;
    const int bn = blockIdx.x * 128;
    const int bm = blockIdx.y * 128;
    const int wm = wid >> 1, wn = wid & 1;
    const int g = lid >> 2, tg = lid & 3;
    const __half* Ap = A;
    const __half* Wp = W;

    float c[2][8][4];
#pragma unroll
    for (int mi = 0; mi < 2; ++mi)
#pragma unroll
        for (int ni = 0; ni < 8; ++ni)
#pragma unroll
            for (int k = 0; k < 4; ++k) c[mi][ni][k] = 0.0f;

    GEMM_MAINLOOP16();

#pragma unroll
    for (int mi = 0; mi < 2; ++mi) {
        const int rowa = bm + wm * 32 + mi * 16 + g;
        const int rowb = rowa + 8;
#pragma unroll
        for (int ni = 0; ni < 8; ++ni) {
            const int col = bn + wn * 64 + ni * 8 + tg * 2;
            const float b0 = bias[col], b1 = bias[col + 1];
            *(float2*)(out + (size_t)rowa * HID + col) =
                make_float2(c[mi][ni][0] + b0, c[mi][ni][1] + b1);
            *(float2*)(out + (size_t)rowb * HID + col) =
                make_float2(c[mi][ni][2] + b0, c[mi][ni][3] + b1);
        }
    }
}

// ---------------------------------------------------------------------------
// FP16 tensor-core flash attention. K-tiles of 32. Fixed-zero-max softmax.
// cp.async double-buffered K, V^T, bias. P goes S-frag -> half2 pack -> PV
// A-frag with NO shuffles (fp16 m16n8k16 layout identity).
// CTA: 128 q, 8 warps x 16 q-rows.
// Smem bytes: Q[128x144] | K0,K1[32x144] | Vt0,Vt1[64x80] | B0,B1[128x144]
// ---------------------------------------------------------------------------
#define QPITCH 144
#define VPITCH 80
#define BPADF  36                                  // floats (144 B)
#define QS_B   0
#define K0_B   (128 * QPITCH)                      // 18432
#define K1_B   (K0_B + 32 * QPITCH)                // 23040
#define V0_B   (K1_B + 32 * QPITCH)                // 27648
#define V1_B   (V0_B + 64 * VPITCH)                // 32768
#define B0_B   (V1_B + 64 * VPITCH)                // 37888
#define B1_B   (B0_B + 128 * BPADF * 4)            // 56320
#define ATTN_SMEM_BYTES (B1_B + 128 * BPADF * 4)   // 74752

#define KT_N   32
#define NTILES (S_LEN / KT_N)                      // 32

__global__ __launch_bounds__(256, 2) void attn_mma(
    const __half* __restrict__ Qg, const __half* __restrict__ Kg,
    const __half* __restrict__ Vt, const float* __restrict__ Bias,
    __half* __restrict__ O)
{
    extern __shared__ float sm[];
    char* smc = (char*)sm;
    const uint32_t sb = smem_u32(sm);
    const uint32_t KbB[2] = { sb + K0_B, sb + K1_B };
    const uint32_t VbB[2] = { sb + V0_B, sb + V1_B };
    const uint32_t BbB[2] = { sb + B0_B, sb + B1_B };
    const char* Kc[2] = { smc + K0_B, smc + K1_B };
    const char* Vc[2] = { smc + V0_B, smc + V1_B };
    const float* Bf[2] = { (const float*)(smc + B0_B), (const float*)(smc + B1_B) };

    const int q0 = blockIdx.x * 128;
    const int h  = blockIdx.y;
    const int b  = blockIdx.z;
    const int bh = b * NH + h;

    const __half* qp = Qg + (size_t)bh * S_LEN * DK + (size_t)q0 * DK;
    const __half* kp = Kg + (size_t)bh * S_LEN * DK;
    const __half* vtp = Vt + (size_t)bh * DK * S_LEN;
    const float* bp = Bias + (size_t)bh * S_LEN * S_LEN + (size_t)q0 * S_LEN;

    const int tid = threadIdx.x;
    const int wid = tid >> 5, lid = tid & 31;
    const int g = lid >> 2, tg = lid & 3;
    const int qb = wid * 16;
    const int qrow0 = q0 + qb + g;

    // Per-tile async loads: K 32x64 fp16 (256 chunks), Vt 64x32 fp16
    // (256 chunks), bias 128x32 fp32 (1024 chunks).
#define LOAD_TILE(st, kt)                                                     \
    do {                                                                      \
        {                                                                     \
            const int row = tid >> 3, off = tid & 7;                          \
            cpasync16(KbB[st] + row * QPITCH + off * 16,                      \
                      kp + (size_t)((kt) * KT_N + row) * 64 + off * 8);       \
        }                                                                     \
        {                                                                     \
            const int row = tid >> 2, off = tid & 3;                          \
            cpasync16(VbB[st] + row * VPITCH + off * 16,                      \
                      vtp + (size_t)row * S_LEN + (kt) * KT_N + off * 8);     \
        }                                                                     \
        const float* bpn = bp + (kt) * KT_N;                                  \
        _Pragma("unroll")                                                     \
        for (int i2 = 0; i2 < 4; ++i2) {                                      \
            const int cidx = tid + i2 * 256;                                  \
            const int row = cidx >> 3, off = cidx & 7;                        \
            cpasync16(BbB[st] + row * (BPADF * 4) + off * 16,                 \
                      bpn + (size_t)row * S_LEN + off * 4);                   \
        }                                                                     \
        cpasync_commit();                                                     \
    } while (0)

    // Prologue: Q tile (128 rows x 128 B = 1024 chunks) + tile 0
#pragma unroll
    for (int i = 0; i < 4; ++i) {
        const int cidx = tid + i * 256;
        const int row = cidx >> 3, off = cidx & 7;
        cpasync16(sb + QS_B + row * QPITCH + off * 16, qp + row * 64 + off * 8);
    }
    LOAD_TILE(0, 0);

    float l0 = 0.0f, l1 = 0.0f;
    float acc[8][4];
#pragma unroll
    for (int ni = 0; ni < 8; ++ni)
#pragma unroll
        for (int j = 0; j < 4; ++j) acc[ni][j] = 0.0f;

    for (int kt = 0; kt < NTILES; ++kt) {
        cpasync_wait0();
        __syncthreads();
        const int cur = kt & 1;

        if (kt + 1 < NTILES) LOAD_TILE(cur ^ 1, kt + 1);

        // S = Q @ K^T  (warp: 16 q x 32 k), fp16 m16n8k16
        float s[4][4];
#pragma unroll
        for (int ni = 0; ni < 4; ++ni)
#pragma unroll
            for (int j = 0; j < 4; ++j) s[ni][j] = 0.0f;
        const char* Kcur = Kc[cur];
#pragma unroll
        for (int kc = 0; kc < 64; kc += 16) {
            uint32_t a[4];
            const char* qa = smc + QS_B + (qb + g) * QPITCH + (kc + 2 * tg) * 2;
            a[0] = *(const uint32_t*)(qa);
            a[1] = *(const uint32_t*)(qa + 8 * QPITCH);
            a[2] = *(const uint32_t*)(qa + 16);
            a[3] = *(const uint32_t*)(qa + 8 * QPITCH + 16);
#pragma unroll
            for (int ni = 0; ni < 4; ++ni) {
                uint32_t bb[2];
                const char* kb2 = Kcur + (ni * 8 + g) * QPITCH + (kc + 2 * tg) * 2;
                bb[0] = *(const uint32_t*)(kb2);
                bb[1] = *(const uint32_t*)(kb2 + 16);
                mma_f16(s[ni], a, bb);
            }
        }

        // mask + bias + exp; pack P to fp16 half2 (A-frag ready, no shuffle)
        const float* Bcur = Bf[cur];
        uint32_t plo[4], phi[4];
#pragma unroll
        for (int ni = 0; ni < 4; ++ni) {
            const int bco = ni * 8 + tg * 2;
            float2 b0 = *(const float2*)(Bcur + (qb + g) * BPADF + bco);
            float2 b1 = *(const float2*)(Bcur + (qb + g + 8) * BPADF + bco);
            const float p00 = fexp((s[ni][0] == 0.0f ? NEGV : s[ni][0]) + b0.x);
            const float p01 = fexp((s[ni][1] == 0.0f ? NEGV : s[ni][1]) + b0.y);
            const float p10 = fexp((s[ni][2] == 0.0f ? NEGV : s[ni][2]) + b1.x);
            const float p11 = fexp((s[ni][3] == 0.0f ? NEGV : s[ni][3]) + b1.y);
            l0 += p00 + p01;
            l1 += p10 + p11;
            __half2 hlo = __float22half2_rn(make_float2(p00, p01));
            __half2 hhi = __float22half2_rn(make_float2(p10, p11));
            plo[ni] = *(const uint32_t*)&hlo;
            phi[ni] = *(const uint32_t*)&hhi;
        }

        // acc += P @ V : fp16 m16n8k16, 2 k-blocks of 16 keys
        const char* Vcur = Vc[cur];
#pragma unroll
        for (int j = 0; j < 2; ++j) {
            uint32_t a[4];
            a[0] = plo[2 * j];
            a[1] = phi[2 * j];
            a[2] = plo[2 * j + 1];
            a[3] = phi[2 * j + 1];
#pragma unroll
            for (int ni = 0; ni < 8; ++ni) {
                uint32_t bb[2];
                const char* vb = Vcur + (ni * 8 + g) * VPITCH + (j * 16 + 2 * tg) * 2;
                bb[0] = *(const uint32_t*)(vb);
                bb[1] = *(const uint32_t*)(vb + 16);
                mma_f16(acc[ni], a, bb);
            }
        }
    }

    // Row sums: single quad reduction at the end.
    l0 += __shfl_xor_sync(0xffffffffu, l0, 1);
    l0 += __shfl_xor_sync(0xffffffffu, l0, 2);
    l1 += __shfl_xor_sync(0xffffffffu, l1, 1);
    l1 += __shfl_xor_sync(0xffffffffu, l1, 2);

    // Epilogue: normalize, fp16 (O-proj A operand), store [b][s][hid]
    const float inv0 = 1.0f / l0;
    const float inv1 = 1.0f / l1;
#pragma unroll
    for (int ni = 0; ni < 8; ++ni) {
        const int col = h * DK + ni * 8 + tg * 2;
        __half* o0 = O + (size_t)(b * S_LEN + qrow0) * HID + col;
        __half* o1 = O + (size_t)(b * S_LEN + qrow0 + 8) * HID + col;
        *(__half2*)o0 = __float22half2_rn(
            make_float2(acc[ni][0] * inv0, acc[ni][1] * inv0));
        *(__half2*)o1 = __float22half2_rn(
            make_float2(acc[ni][2] * inv1, acc[ni][3] * inv1));
    }
}

// ---------------------------------------------------------------------------
extern "C" void kernel_launch(void* const* d_in, const int* in_sizes, int n_in,
                              void* d_out, int out_size)
{
    const float* batch = (const float*)d_in[0];
    const float* bias  = (const float*)d_in[1];
    const float* Wq = (const float*)d_in[2];
    const float* bq = (const float*)d_in[3];
    const float* Wk = (const float*)d_in[4];
    const float* bk = (const float*)d_in[5];
    const float* Wv = (const float*)d_in[6];
    const float* bv = (const float*)d_in[7];
    const float* Wo = (const float*)d_in[8];
    const float* bo = (const float*)d_in[9];
    float* out = (float*)d_out;

    __half *qptr, *kptr, *vtptr, *aptr, *xptr, *wqp, *wkp, *wvp, *wop;
    cudaGetSymbolAddress((void**)&qptr, g_q16);
    cudaGetSymbolAddress((void**)&kptr, g_k16);
    cudaGetSymbolAddress((void**)&vtptr, g_vt16);
    cudaGetSymbolAddress((void**)&aptr, g_att16);
    cudaGetSymbolAddress((void**)&xptr, g_x16);
    cudaGetSymbolAddress((void**)&wqp, g_wq16);
    cudaGetSymbolAddress((void**)&wkp, g_wk16);
    cudaGetSymbolAddress((void**)&wvp, g_wv16);
    cudaGetSymbolAddress((void**)&wop, g_wo16);

    static int attr_set = 0;
    if (!attr_set) {
        cudaFuncSetAttribute(gemm_qkv,
                             cudaFuncAttributeMaxDynamicSharedMemorySize,
                             GEMM_SMEM_BYTES);
        cudaFuncSetAttribute(gemm_o,
                             cudaFuncAttributeMaxDynamicSharedMemorySize,
                             GEMM_SMEM_BYTES);
        cudaFuncSetAttribute(attn_mma,
                             cudaFuncAttributeMaxDynamicSharedMemorySize,
                             ATTN_SMEM_BYTES);
        attr_set = 1;
    }

    const int totalG = G8X + 4 * G8W;
    round_all16<<<totalG / 256, 256>>>(
        (const float4*)batch, (const float4*)Wq, (const float4*)Wk,
        (const float4*)Wv, (const float4*)Wo,
        xptr, wqp, wkp, wvp, wop);

    dim3 qkvgrid(24, 32);
    gemm_qkv<<<qkvgrid, 256, GEMM_SMEM_BYTES>>>(xptr, wqp, wkp, wvp,
                                                bq, bk, bv, qptr, kptr, vtptr);

    dim3 agrid(S_LEN / 128, NH, BATCH);
    attn_mma<<<agrid, 256, ATTN_SMEM_BYTES>>>(qptr, kptr, vtptr, bias, aptr);

    dim3 ogrid(HID / 128, M_TOT / 128);
    gemm_o<<<ogrid, 256, GEMM_SMEM_BYTES>>>(aptr, wop, bo, out);
}